// round 6
// baseline (speedup 1.0000x reference)
#include <cuda_runtime.h>
#include <cuda_bf16.h>
#include <cstdint>

// GCN 2-layer, N=100000, E=1.6M, 128 -> 128(relu) -> 64 -> softmax.
// R6: row-pair-packed f32x2 GEMM (transposed Xs + duplicated W, no movs),
//     8-deep MLP agg kernels, CSR build || gemm1, gemm2(A) || agg1(B).

#define GCN_N 100000
#define GCN_E 1600000
#define D_IN 128
#define D_HID 128
#define D_OUT 64

__device__ int   g_degi[GCN_N];
__device__ int   g_rowptr[GCN_N + 1];
__device__ int   g_cursor[GCN_N];
__device__ int   g_csr[GCN_E];
__device__ float g_norm[GCN_N];
__device__ float g_h1[(size_t)GCN_N * D_HID];
__device__ float g_a1[(size_t)GCN_N * D_HID];
__device__ float g_h2[(size_t)GCN_N * D_OUT];

// ---------------------------------------------------------------------------
__global__ void zero_int_kernel(int* __restrict__ p, int n) {
    int i = blockIdx.x * blockDim.x + threadIdx.x;
    if (i < n) p[i] = 0;
}

__global__ void deg_kernel(const int* __restrict__ dst, int* __restrict__ deg, int ne) {
    int t = blockIdx.x * blockDim.x + threadIdx.x;
    int ne4 = ne >> 2;
    if (t < ne4) {
        int4 d = ((const int4*)dst)[t];
        atomicAdd(&deg[d.x], 1);
        atomicAdd(&deg[d.y], 1);
        atomicAdd(&deg[d.z], 1);
        atomicAdd(&deg[d.w], 1);
    } else {
        int e = ne4 * 4 + (t - ne4);
        if (e < ne) atomicAdd(&deg[dst[e]], 1);
    }
}

__global__ __launch_bounds__(1024) void scan_kernel(
    const int* __restrict__ deg, int* __restrict__ rowptr,
    int* __restrict__ cursor, float* __restrict__ nrm, int n)
{
    __shared__ int sums[1024];
    const int t = threadIdx.x;
    const int chunk = (n + 1023) / 1024;
    int begin = t * chunk;
    int end = begin + chunk; if (end > n) end = n;
    if (begin > n) begin = n;

    int s = 0;
    for (int i = begin; i < end; i++) s += deg[i];
    sums[t] = s;
    __syncthreads();
    for (int d = 1; d < 1024; d <<= 1) {
        int v = (t >= d) ? sums[t - d] : 0;
        __syncthreads();
        sums[t] += v;
        __syncthreads();
    }
    int off = sums[t] - s;
    for (int i = begin; i < end; i++) {
        rowptr[i] = off;
        cursor[i] = off;
        int dv = deg[i];
        nrm[i] = rsqrtf((float)dv + 1.0f);
        off += dv;
    }
    if (begin < end && end == n) rowptr[n] = off;
}

__global__ void fill_kernel(const int* __restrict__ src, const int* __restrict__ dst,
                            int* __restrict__ cursor, int* __restrict__ csr, int ne)
{
    int t = blockIdx.x * blockDim.x + threadIdx.x;
    int ne4 = ne >> 2;
    if (t < ne4) {
        int4 s = ((const int4*)src)[t];
        int4 d = ((const int4*)dst)[t];
        int p0 = atomicAdd(&cursor[d.x], 1);
        int p1 = atomicAdd(&cursor[d.y], 1);
        int p2 = atomicAdd(&cursor[d.z], 1);
        int p3 = atomicAdd(&cursor[d.w], 1);
        csr[p0] = s.x; csr[p1] = s.y; csr[p2] = s.z; csr[p3] = s.w;
    } else {
        int e = ne4 * 4 + (t - ne4);
        if (e < ne) {
            int p = atomicAdd(&cursor[dst[e]], 1);
            csr[p] = src[e];
        }
    }
}

// ---------------------------------------------------------------------------
// GEMM: H[r, 0..NC) = X[r, 0..128) @ W[128, NC]
// 64-row blocks, 256 threads (32,8). Thread: 8 rows (4 row-pairs) x TN cols.
// f32x2 packed FMA over row pairs: A-pair = LDS.64 of transposed Xs (broadcast),
// B = LDS.64 of duplicated W (no packing movs).
template <int NC>
__global__ __launch_bounds__(256) void gemm_kernel(
    const float* __restrict__ X, const float* __restrict__ W,
    float* __restrict__ H, int nrows)
{
    constexpr int TN = NC / 32;   // 4 (NC=128) or 2 (NC=64)
    __shared__ __align__(16) float XsT[128 * 64];        // [k][r], 32KB
    __shared__ __align__(16) float2 Wdup[32 * NC];       // [kk][c] = {w,w}

    const int row0 = blockIdx.x * 64;
    const int tid = threadIdx.y * 32 + threadIdx.x;
    const int tx = threadIdx.x;
    const int r0 = threadIdx.y * 8;

    // load X tile transposed: element (r, k4..k4+3)
    if (row0 + 64 <= nrows) {
        for (int i = tid; i < 64 * 32; i += 256) {
            int r = i & 63;
            int k4 = (i >> 6) * 4;
            float4 v = *(const float4*)(X + (size_t)(row0 + r) * 128 + k4);
            XsT[(k4 + 0) * 64 + r] = v.x;
            XsT[(k4 + 1) * 64 + r] = v.y;
            XsT[(k4 + 2) * 64 + r] = v.z;
            XsT[(k4 + 3) * 64 + r] = v.w;
        }
    } else {
        for (int i = tid; i < 64 * 128; i += 256) {
            int r = i & 63;
            int k = i >> 6;
            int gr = row0 + r;
            XsT[k * 64 + r] = (gr < nrows) ? X[(size_t)gr * 128 + k] : 0.f;
        }
    }

    unsigned long long accP[4][TN];
    #pragma unroll
    for (int p = 0; p < 4; p++)
        #pragma unroll
        for (int j = 0; j < TN; j++) accP[p][j] = 0ull;

    const unsigned long long* XsT64 = (const unsigned long long*)XsT;
    const unsigned long long* Wdup64 = (const unsigned long long*)Wdup;

    #pragma unroll
    for (int kc = 0; kc < 4; kc++) {
        __syncthreads();
        for (int i = tid; i < 32 * NC; i += 256) {
            int kk = i / NC, c = i % NC;
            float w = W[(size_t)(kc * 32 + kk) * NC + c];
            Wdup[kk * NC + c] = make_float2(w, w);
        }
        __syncthreads();
        #pragma unroll
        for (int kk = 0; kk < 32; kk++) {
            unsigned long long bP[TN];
            #pragma unroll
            for (int j = 0; j < TN; j++)
                bP[j] = Wdup64[kk * NC + tx + 32 * j];
            unsigned long long aP[4];
            #pragma unroll
            for (int p = 0; p < 4; p++)
                aP[p] = XsT64[((kc * 32 + kk) * 64 + r0) / 2 + p];
            #pragma unroll
            for (int p = 0; p < 4; p++)
                #pragma unroll
                for (int j = 0; j < TN; j++)
                    asm("fma.rn.f32x2 %0, %1, %2, %0;"
                        : "+l"(accP[p][j]) : "l"(aP[p]), "l"(bP[j]));
        }
    }

    #pragma unroll
    for (int p = 0; p < 4; p++) {
        int gr0 = row0 + r0 + 2 * p;
        #pragma unroll
        for (int j = 0; j < TN; j++) {
            unsigned int lo_u, hi_u;
            asm("mov.b64 {%0, %1}, %2;" : "=r"(lo_u), "=r"(hi_u) : "l"(accP[p][j]));
            if (gr0 < nrows)     H[(size_t)gr0 * NC + tx + 32 * j]       = __uint_as_float(lo_u);
            if (gr0 + 1 < nrows) H[(size_t)(gr0 + 1) * NC + tx + 32 * j] = __uint_as_float(hi_u);
        }
    }
}

// ---------------------------------------------------------------------------
// Layer-1 aggregate + finalize over node range [node0, node0+cnt):
//   a1[v] = relu( nrm[v]*( h1[v]*nrm[v] + sum_u h1[u]*nrm[u] ) + b1 )
// One warp per node, float4 per lane, 8-deep gather MLP, 4 acc chains.
__global__ __launch_bounds__(256) void agg1_kernel(
    const float* __restrict__ h1, const int* __restrict__ csr,
    const int* __restrict__ rowptr, const float* __restrict__ nrm,
    const float* __restrict__ b1, float* __restrict__ a1, int node0, int cnt)
{
    int idx = blockIdx.x * 8 + threadIdx.y;
    if (idx >= cnt) return;
    int node = node0 + idx;
    int lane = threadIdx.x;
    const float4* H4 = (const float4*)h1;

    float nself = nrm[node];
    float4 sv = H4[(size_t)node * 32 + lane];
    float4 acc0, acc1, acc2, acc3;
    acc0.x = sv.x * nself; acc0.y = sv.y * nself;
    acc0.z = sv.z * nself; acc0.w = sv.w * nself;
    acc1 = make_float4(0.f, 0.f, 0.f, 0.f);
    acc2 = make_float4(0.f, 0.f, 0.f, 0.f);
    acc3 = make_float4(0.f, 0.f, 0.f, 0.f);

    int beg = rowptr[node], end = rowptr[node + 1];
    int j = beg;
    for (; j + 8 <= end; j += 8) {
        int s0 = csr[j],     s1 = csr[j + 1], s2 = csr[j + 2], s3 = csr[j + 3];
        int s4 = csr[j + 4], s5 = csr[j + 5], s6 = csr[j + 6], s7 = csr[j + 7];
        float4 v0 = H4[(size_t)s0 * 32 + lane];
        float4 v1 = H4[(size_t)s1 * 32 + lane];
        float4 v2 = H4[(size_t)s2 * 32 + lane];
        float4 v3 = H4[(size_t)s3 * 32 + lane];
        float4 v4 = H4[(size_t)s4 * 32 + lane];
        float4 v5 = H4[(size_t)s5 * 32 + lane];
        float4 v6 = H4[(size_t)s6 * 32 + lane];
        float4 v7 = H4[(size_t)s7 * 32 + lane];
        float n0 = nrm[s0], n1 = nrm[s1], n2 = nrm[s2], n3 = nrm[s3];
        float n4 = nrm[s4], n5 = nrm[s5], n6 = nrm[s6], n7 = nrm[s7];
        acc0.x = fmaf(v0.x, n0, acc0.x); acc0.y = fmaf(v0.y, n0, acc0.y);
        acc0.z = fmaf(v0.z, n0, acc0.z); acc0.w = fmaf(v0.w, n0, acc0.w);
        acc1.x = fmaf(v1.x, n1, acc1.x); acc1.y = fmaf(v1.y, n1, acc1.y);
        acc1.z = fmaf(v1.z, n1, acc1.z); acc1.w = fmaf(v1.w, n1, acc1.w);
        acc2.x = fmaf(v2.x, n2, acc2.x); acc2.y = fmaf(v2.y, n2, acc2.y);
        acc2.z = fmaf(v2.z, n2, acc2.z); acc2.w = fmaf(v2.w, n2, acc2.w);
        acc3.x = fmaf(v3.x, n3, acc3.x); acc3.y = fmaf(v3.y, n3, acc3.y);
        acc3.z = fmaf(v3.z, n3, acc3.z); acc3.w = fmaf(v3.w, n3, acc3.w);
        acc0.x = fmaf(v4.x, n4, acc0.x); acc0.y = fmaf(v4.y, n4, acc0.y);
        acc0.z = fmaf(v4.z, n4, acc0.z); acc0.w = fmaf(v4.w, n4, acc0.w);
        acc1.x = fmaf(v5.x, n5, acc1.x); acc1.y = fmaf(v5.y, n5, acc1.y);
        acc1.z = fmaf(v5.z, n5, acc1.z); acc1.w = fmaf(v5.w, n5, acc1.w);
        acc2.x = fmaf(v6.x, n6, acc2.x); acc2.y = fmaf(v6.y, n6, acc2.y);
        acc2.z = fmaf(v6.z, n6, acc2.z); acc2.w = fmaf(v6.w, n6, acc2.w);
        acc3.x = fmaf(v7.x, n7, acc3.x); acc3.y = fmaf(v7.y, n7, acc3.y);
        acc3.z = fmaf(v7.z, n7, acc3.z); acc3.w = fmaf(v7.w, n7, acc3.w);
    }
    for (; j < end; j++) {
        int s = csr[j];
        float nn = nrm[s];
        float4 v = H4[(size_t)s * 32 + lane];
        acc0.x = fmaf(v.x, nn, acc0.x); acc0.y = fmaf(v.y, nn, acc0.y);
        acc0.z = fmaf(v.z, nn, acc0.z); acc0.w = fmaf(v.w, nn, acc0.w);
    }
    float sx = (acc0.x + acc1.x) + (acc2.x + acc3.x);
    float sy = (acc0.y + acc1.y) + (acc2.y + acc3.y);
    float sz = (acc0.z + acc1.z) + (acc2.z + acc3.z);
    float sw = (acc0.w + acc1.w) + (acc2.w + acc3.w);
    float4 bb = ((const float4*)b1)[lane];
    float4 r;
    r.x = fmaxf(fmaf(sx, nself, bb.x), 0.f);
    r.y = fmaxf(fmaf(sy, nself, bb.y), 0.f);
    r.z = fmaxf(fmaf(sz, nself, bb.z), 0.f);
    r.w = fmaxf(fmaf(sw, nself, bb.w), 0.f);
    ((float4*)a1)[(size_t)node * 32 + lane] = r;
}

// Layer-2 aggregate + softmax fused; float2 per lane, 8-deep MLP.
__global__ __launch_bounds__(256) void agg2_kernel(
    const float* __restrict__ h2, const int* __restrict__ csr,
    const int* __restrict__ rowptr, const float* __restrict__ nrm,
    const float* __restrict__ b2, float* __restrict__ out, int n)
{
    int node = blockIdx.x * 8 + threadIdx.y;
    if (node >= n) return;
    int lane = threadIdx.x;
    const float2* H2 = (const float2*)h2;

    float nself = nrm[node];
    float2 sv = H2[(size_t)node * 32 + lane];
    float2 acc0, acc1, acc2, acc3;
    acc0.x = sv.x * nself; acc0.y = sv.y * nself;
    acc1 = make_float2(0.f, 0.f);
    acc2 = make_float2(0.f, 0.f);
    acc3 = make_float2(0.f, 0.f);

    int beg = rowptr[node], end = rowptr[node + 1];
    int j = beg;
    for (; j + 8 <= end; j += 8) {
        int s0 = csr[j],     s1 = csr[j + 1], s2 = csr[j + 2], s3 = csr[j + 3];
        int s4 = csr[j + 4], s5 = csr[j + 5], s6 = csr[j + 6], s7 = csr[j + 7];
        float2 v0 = H2[(size_t)s0 * 32 + lane];
        float2 v1 = H2[(size_t)s1 * 32 + lane];
        float2 v2 = H2[(size_t)s2 * 32 + lane];
        float2 v3 = H2[(size_t)s3 * 32 + lane];
        float2 v4 = H2[(size_t)s4 * 32 + lane];
        float2 v5 = H2[(size_t)s5 * 32 + lane];
        float2 v6 = H2[(size_t)s6 * 32 + lane];
        float2 v7 = H2[(size_t)s7 * 32 + lane];
        float n0 = nrm[s0], n1 = nrm[s1], n2 = nrm[s2], n3 = nrm[s3];
        float n4 = nrm[s4], n5 = nrm[s5], n6 = nrm[s6], n7 = nrm[s7];
        acc0.x = fmaf(v0.x, n0, acc0.x); acc0.y = fmaf(v0.y, n0, acc0.y);
        acc1.x = fmaf(v1.x, n1, acc1.x); acc1.y = fmaf(v1.y, n1, acc1.y);
        acc2.x = fmaf(v2.x, n2, acc2.x); acc2.y = fmaf(v2.y, n2, acc2.y);
        acc3.x = fmaf(v3.x, n3, acc3.x); acc3.y = fmaf(v3.y, n3, acc3.y);
        acc0.x = fmaf(v4.x, n4, acc0.x); acc0.y = fmaf(v4.y, n4, acc0.y);
        acc1.x = fmaf(v5.x, n5, acc1.x); acc1.y = fmaf(v5.y, n5, acc1.y);
        acc2.x = fmaf(v6.x, n6, acc2.x); acc2.y = fmaf(v6.y, n6, acc2.y);
        acc3.x = fmaf(v7.x, n7, acc3.x); acc3.y = fmaf(v7.y, n7, acc3.y);
    }
    for (; j < end; j++) {
        int s = csr[j];
        float nn = nrm[s];
        float2 v = H2[(size_t)s * 32 + lane];
        acc0.x = fmaf(v.x, nn, acc0.x); acc0.y = fmaf(v.y, nn, acc0.y);
    }
    float2 bb = ((const float2*)b2)[lane];
    float vx = fmaf((acc0.x + acc1.x) + (acc2.x + acc3.x), nself, bb.x);
    float vy = fmaf((acc0.y + acc1.y) + (acc2.y + acc3.y), nself, bb.y);

    float m = fmaxf(vx, vy);
    #pragma unroll
    for (int o = 16; o; o >>= 1) m = fmaxf(m, __shfl_xor_sync(0xffffffffu, m, o));
    float ex = __expf(vx - m);
    float ey = __expf(vy - m);
    float s = ex + ey;
    #pragma unroll
    for (int o = 16; o; o >>= 1) s += __shfl_xor_sync(0xffffffffu, s, o);
    float inv = 1.0f / s;
    float2 r;
    r.x = ex * inv;
    r.y = ey * inv;
    ((float2*)out)[(size_t)node * 32 + lane] = r;
}

// ---------------------------------------------------------------------------
static cudaStream_t g_side = nullptr;
static cudaEvent_t g_evFork = nullptr, g_evJoin = nullptr;
static cudaEvent_t g_evA = nullptr, g_evG2A = nullptr;

extern "C" void kernel_launch(void* const* d_in, const int* in_sizes, int n_in,
                              void* d_out, int out_size)
{
    const float* x = (const float*)d_in[0];
    const int* edge_index = (const int*)d_in[1];
    const float* W1 = (const float*)d_in[2];
    const float* b1 = (const float*)d_in[3];
    const float* W2 = (const float*)d_in[4];
    const float* b2 = (const float*)d_in[5];
    float* out = (float*)d_out;

    const int n = in_sizes[0] / D_IN;
    const int ne = in_sizes[1] / 2;
    const int* src = edge_index;
    const int* dst = edge_index + ne;

    int *p_degi, *p_rowptr, *p_cursor, *p_csr;
    float *p_norm, *p_h1, *p_a1, *p_h2;
    cudaGetSymbolAddress((void**)&p_degi, g_degi);
    cudaGetSymbolAddress((void**)&p_rowptr, g_rowptr);
    cudaGetSymbolAddress((void**)&p_cursor, g_cursor);
    cudaGetSymbolAddress((void**)&p_csr, g_csr);
    cudaGetSymbolAddress((void**)&p_norm, g_norm);
    cudaGetSymbolAddress((void**)&p_h1, g_h1);
    cudaGetSymbolAddress((void**)&p_a1, g_a1);
    cudaGetSymbolAddress((void**)&p_h2, g_h2);

    if (g_side == nullptr) {
        cudaStreamCreateWithFlags(&g_side, cudaStreamNonBlocking);
        cudaEventCreateWithFlags(&g_evFork, cudaEventDisableTiming);
        cudaEventCreateWithFlags(&g_evJoin, cudaEventDisableTiming);
        cudaEventCreateWithFlags(&g_evA, cudaEventDisableTiming);
        cudaEventCreateWithFlags(&g_evG2A, cudaEventDisableTiming);
    }

    dim3 tb(32, 8);
    const int nthr4 = ne / 4 + 4;  // covers int4 body + remainder lanes

    // node split for agg1/gemm2 pipelining (nA multiple of 64)
    const int nA = ((n / 2) / 64) * 64;
    const int nB = n - nA;

    // Fork: CSR build on side stream || gemm1 on main.
    cudaEventRecord(g_evFork, 0);
    cudaStreamWaitEvent(g_side, g_evFork, 0);

    zero_int_kernel<<<(n + 255) / 256, 256, 0, g_side>>>(p_degi, n);
    deg_kernel<<<(nthr4 + 255) / 256, 256, 0, g_side>>>(dst, p_degi, ne);
    scan_kernel<<<1, 1024, 0, g_side>>>(p_degi, p_rowptr, p_cursor, p_norm, n);
    fill_kernel<<<(nthr4 + 255) / 256, 256, 0, g_side>>>(src, dst, p_cursor, p_csr, ne);
    cudaEventRecord(g_evJoin, g_side);

    gemm_kernel<D_HID><<<(n + 63) / 64, tb>>>(x, W1, p_h1, n);

    // main waits for CSR
    cudaStreamWaitEvent(0, g_evJoin, 0);

    // agg1 first half, then fork gemm2(A) on side while agg1(B) runs on main
    agg1_kernel<<<(nA + 7) / 8, tb>>>(p_h1, p_csr, p_rowptr, p_norm, b1, p_a1, 0, nA);
    cudaEventRecord(g_evA, 0);
    cudaStreamWaitEvent(g_side, g_evA, 0);
    gemm_kernel<D_OUT><<<nA / 64, tb, 0, g_side>>>(p_a1, W2, p_h2, nA);
    cudaEventRecord(g_evG2A, g_side);

    agg1_kernel<<<(nB + 7) / 8, tb>>>(p_h1, p_csr, p_rowptr, p_norm, b1, p_a1, nA, nB);
    gemm_kernel<D_OUT><<<(nB + 63) / 64, tb>>>(p_a1 + (size_t)nA * D_HID, W2,
                                               p_h2 + (size_t)nA * D_OUT, nB);

    // agg2 needs all of h2
    cudaStreamWaitEvent(0, g_evG2A, 0);
    agg2_kernel<<<(n + 7) / 8, tb>>>(p_h2, p_csr, p_rowptr, p_norm, b2, out, n);
}